// round 1
// baseline (speedup 1.0000x reference)
#include <cuda_runtime.h>

// Pyramid Givens circuit, n = m = 512.
// Layer t in [0, 1021): gates on pairs (i, i+1) for i ≡ t (mod 2), 0 <= i <= min(t, 1020 - t).
// Theta index for gate (t, i): q = (t+i)/2, tidx = q*(q+1)/2 + q - i.
// Gate: a' = c*a + s*b ; b' = c*b - s*a  (a = wire i, b = wire i+1).

#define T_LAYERS 1021
#define T_PAD    1032          // padded so pipelined prefetch never goes OOB (max read layer = 1025)
#define B_ROWS   256
#define N_WIRES  512

// cs table: per layer, 256 gate slots (slot s -> wire i = 2s + (t&1)), identity (1,0) when inactive.
// Transposed layout for coalesced warp loads:
//   slot s: L = s>>3 (lane), w = s&7, j = w>>1, e = w&1
//   float2 index = t*256 + j*64 + L*2 + e   (== float4 index t*128 + j*32 + L, halves e=0/1)
__device__ float4 g_cs4[T_PAD * 128];   // ~2.1 MB scratch

__global__ void build_cs_kernel(const float* __restrict__ thetas) {
    int t = blockIdx.x;       // 0..1020
    int s = threadIdx.x;      // 0..255
    int p = t & 1;
    int i = 2 * s + p;
    int imax = min(t, 1020 - t);
    float c = 1.0f, sn = 0.0f;
    if (i <= imax) {
        int q = (t + i) >> 1;
        int tidx = (q * (q + 1)) / 2 + q - i;
        float th = __ldg(&thetas[tidx]);
        sincosf(th, &sn, &c);
    }
    int L = s >> 3;
    int w = s & 7;
    int j = w >> 1;
    int e = w & 1;
    float2* base = reinterpret_cast<float2*>(g_cs4);
    base[t * 256 + j * 64 + L * 2 + e] = make_float2(c, sn);
}

__device__ __forceinline__ void rot(float& a, float& b, float c, float s) {
    float na = fmaf(c, a, s * b);
    float nb = fmaf(c, b, -(s * a));
    a = na;
    b = nb;
}

// One warp per batch row. Lane L owns wires [16L, 16L+15] in registers.
// Even layers: 8 in-register rotations. Odd layers: 7 in-register + 1 boundary via 2 shuffles.
// cs loads pipelined through 3 (even,odd) register buffer pairs (6-layer lookahead).
__global__ void __launch_bounds__(64, 1) apply_kernel(
    const float* __restrict__ x,
    const float* __restrict__ bias,
    float* __restrict__ out)
{
    const int lane = threadIdx.x & 31;
    const int row  = blockIdx.x * 2 + (threadIdx.x >> 5);

    float v[16];
    {
        const float4* xr = reinterpret_cast<const float4*>(x + (size_t)row * N_WIRES) + lane * 4;
        #pragma unroll
        for (int j = 0; j < 4; ++j) {
            float4 f = xr[j];
            v[4*j+0] = f.x; v[4*j+1] = f.y; v[4*j+2] = f.z; v[4*j+3] = f.w;
        }
    }

    const float4* cs4 = g_cs4 + lane;   // + t*128 + j*32

    float4 bE[3][4], bO[3][4];
    #define LDCS(dst, tt) { const float4* p_ = cs4 + (tt) * 128; \
        (dst)[0] = p_[0]; (dst)[1] = p_[32]; (dst)[2] = p_[64]; (dst)[3] = p_[96]; }

    LDCS(bE[0], 0) LDCS(bO[0], 1)
    LDCS(bE[1], 2) LDCS(bO[1], 3)
    LDCS(bE[2], 4) LDCS(bO[2], 5)

    int t = 0;
    #pragma unroll 1
    for (int it = 0; it < 170; ++it) {      // 170 * 6 = 1020 layers here, +1 epilogue layer
        #pragma unroll
        for (int u = 0; u < 3; ++u) {
            // ---- even layer (t + 2u) ----
            {
                float4* f = bE[u];
                #pragma unroll
                for (int g2 = 0; g2 < 4; ++g2) {
                    rot(v[4*g2+0], v[4*g2+1], f[g2].x, f[g2].y);
                    rot(v[4*g2+2], v[4*g2+3], f[g2].z, f[g2].w);
                }
            }
            // ---- odd layer (t + 2u + 1) ----
            {
                float4* f = bO[u];
                float bIn = __shfl_down_sync(0xffffffffu, v[0], 1); // neighbor's wire 16(L+1)
                rot(v[1],  v[2],  f[0].x, f[0].y);
                rot(v[3],  v[4],  f[0].z, f[0].w);
                rot(v[5],  v[6],  f[1].x, f[1].y);
                rot(v[7],  v[8],  f[1].z, f[1].w);
                rot(v[9],  v[10], f[2].x, f[2].y);
                rot(v[11], v[12], f[2].z, f[2].w);
                rot(v[13], v[14], f[3].x, f[3].y);
                // boundary gate (16L+15, 16L+16); identity cs at wire 511 makes lane 31 a no-op
                float a  = v[15];
                float c7 = f[3].z, s7 = f[3].w;
                v[15]      = fmaf(c7, a,   s7 * bIn);
                float bOut = fmaf(c7, bIn, -(s7 * a));
                float nv0 = __shfl_up_sync(0xffffffffu, bOut, 1);
                if (lane != 0) v[0] = nv0;  // lane 0 keeps wire 0 (no gate at i = -1)
            }
            // prefetch pair (t + 2u + 6, t + 2u + 7); padded table keeps reads in-bounds
            LDCS(bE[u], t + 6 + 2*u)
            LDCS(bO[u], t + 7 + 2*u)
        }
        t += 6;
    }

    // epilogue: layer 1020 (even), sitting in bE[0]
    {
        float4* f = bE[0];
        #pragma unroll
        for (int g2 = 0; g2 < 4; ++g2) {
            rot(v[4*g2+0], v[4*g2+1], f[g2].x, f[g2].y);
            rot(v[4*g2+2], v[4*g2+3], f[g2].z, f[g2].w);
        }
    }

    // write out + bias
    {
        const float4* bb = reinterpret_cast<const float4*>(bias) + lane * 4;
        float4* outr = reinterpret_cast<float4*>(out + (size_t)row * N_WIRES) + lane * 4;
        #pragma unroll
        for (int j = 0; j < 4; ++j) {
            float4 bf = bb[j];
            float4 o;
            o.x = v[4*j+0] + bf.x;
            o.y = v[4*j+1] + bf.y;
            o.z = v[4*j+2] + bf.z;
            o.w = v[4*j+3] + bf.w;
            outr[j] = o;
        }
    }
    #undef LDCS
}

extern "C" void kernel_launch(void* const* d_in, const int* in_sizes, int n_in,
                              void* d_out, int out_size) {
    const float* x      = (const float*)d_in[0];
    const float* thetas = (const float*)d_in[1];
    const float* bias   = (const float*)d_in[2];
    float* out = (float*)d_out;

    build_cs_kernel<<<T_LAYERS, 256>>>(thetas);

    int B = in_sizes[0] / N_WIRES;   // 256
    apply_kernel<<<B / 2, 64>>>(x, bias, out);
}

// round 2
// speedup vs baseline: 1.0363x; 1.0363x over previous
#include <cuda_runtime.h>

// Pyramid Givens circuit, n = m = 512, B = 256.
// Layer t in [0,1021): gates (i,i+1) for i ≡ t (mod 2), 0 <= i <= min(t, 1020-t).
// theta index: q=(t+i)/2, tidx = q(q+1)/2 + q - i.
// Gate: a' = c*a + s*b ; b' = c*b - s*a.

#define T_LAYERS 1021
#define T_PAD    1032          // prefetch pipeline reads up to layer 1025
#define N_WIRES  512

typedef unsigned long long ull;

// Packed cs table. Lane L owns wires [16L,16L+15], held as P[k]=(v_k,v_{k+8}), k=0..7.
// Per (layer t, lane, packed-rot r): double2 = { c2 (f32x2 payload), s2 (f32x2 payload) }.
//  even t, r=0..3: rot on (P_2r,P_2r+1): lo gate wire 16L+2r, hi gate wire 16L+2r+8
//  odd t,  r=0..2: rot on (P_2r+1,P_2r+2): lo gate 16L+2r+1, hi gate 16L+2r+9
//  odd t,  r=3:    boundary rot on (P7, Q=(v8,v16)): lo gate 16L+7, hi gate 16L+15
// Inactive gates stored as identity (c=1,s=0).
__device__ double2 g_tab[T_PAD][4][32];     // ~2.1 MB
// Left-gate cs for odd layers: gate at wire 16L-1 (lane 0 -> identity).
__device__ float2  g_left[T_PAD][32];       // ~0.26 MB

__device__ __forceinline__ float2 cs_of(const float* __restrict__ th, int t, int i) {
    if (t <= 1020 && i >= 0 && i <= t && i <= 1020 - t && (((i ^ t) & 1) == 0)) {
        int q = (t + i) >> 1;
        int tidx = (q * (q + 1)) / 2 + q - i;
        float s, c;
        sincosf(th[tidx], &s, &c);
        return make_float2(c, s);
    }
    return make_float2(1.0f, 0.0f);
}

__global__ void build_cs_kernel(const float* __restrict__ thetas) {
    int t    = blockIdx.x;          // 0..T_PAD-1 (padding layers -> identity)
    int r    = threadIdx.x >> 5;    // 0..3
    int lane = threadIdx.x & 31;
    int base = 16 * lane;
    int ilo, ihi;
    if ((t & 1) == 0)      { ilo = base + 2 * r;     ihi = ilo + 8; }
    else if (r < 3)        { ilo = base + 2 * r + 1; ihi = ilo + 8; }
    else                   { ilo = base + 7;         ihi = base + 15; }
    float2 a = cs_of(thetas, t, ilo);
    float2 b = cs_of(thetas, t, ihi);
    float2* dst = reinterpret_cast<float2*>(&g_tab[t][r][lane]);
    dst[0] = make_float2(a.x, b.x);   // c2 = (c_lo, c_hi)
    dst[1] = make_float2(a.y, b.y);   // s2 = (s_lo, s_hi)
    if (r == 3) {
        g_left[t][lane] = (lane == 0) ? make_float2(1.0f, 0.0f)
                                      : cs_of(thetas, t, base - 1);
    }
}

// ---- f32x2 helpers ----
__device__ __forceinline__ ull mul2(ull a, ull b) {
    ull d; asm("mul.rn.f32x2 %0, %1, %2;" : "=l"(d) : "l"(a), "l"(b)); return d;
}
__device__ __forceinline__ ull fma2(ull a, ull b, ull c) {
    ull d; asm("fma.rn.f32x2 %0, %1, %2, %3;" : "=l"(d) : "l"(a), "l"(b), "l"(c)); return d;
}
__device__ __forceinline__ float lo_f(ull p) {
    float lo, hi; asm("mov.b64 {%0, %1}, %2;" : "=f"(lo), "=f"(hi) : "l"(p)); return lo;
}
__device__ __forceinline__ float hi_f(ull p) {
    float lo, hi; asm("mov.b64 {%0, %1}, %2;" : "=f"(lo), "=f"(hi) : "l"(p)); return hi;
}
__device__ __forceinline__ ull pk(float lo, float hi) {
    ull d; asm("mov.b64 %0, {%1, %2};" : "=l"(d) : "f"(lo), "f"(hi)); return d;
}

#define SGNMASK 0x8000000080000000ULL

// Packed Givens: a' = c*a + s*b ; b' = c*b - s*a   (4 fma-pipe ops + 1 xor)
__device__ __forceinline__ void rotp(ull& a, ull& b, double2 cs) {
    ull c2 = __double_as_longlong(cs.x);
    ull s2 = __double_as_longlong(cs.y);
    ull t1 = mul2(s2, b);
    ull na = fma2(c2, a, t1);
    ull t2 = mul2(s2, a) ^ SGNMASK;      // -s*a
    b = fma2(c2, b, t2);
    a = na;
}

// One warp per batch row, 2 warps per CTA (2 warps/SM over 128 SMs).
__global__ void __launch_bounds__(64, 1) apply_kernel(
    const float* __restrict__ x,
    const float* __restrict__ bias,
    float* __restrict__ out)
{
    const int lane = threadIdx.x & 31;
    const int row  = blockIdx.x * 2 + (threadIdx.x >> 5);

    // Load row, pack P[k] = (v_k, v_{k+8})
    ull P[8];
    {
        float v[16];
        const float4* xr = reinterpret_cast<const float4*>(x + (size_t)row * N_WIRES) + lane * 4;
        #pragma unroll
        for (int j = 0; j < 4; ++j) {
            float4 f = xr[j];
            v[4*j+0] = f.x; v[4*j+1] = f.y; v[4*j+2] = f.z; v[4*j+3] = f.w;
        }
        #pragma unroll
        for (int k = 0; k < 8; ++k) P[k] = pk(v[k], v[k + 8]);
    }

    const double2* tab  = &g_tab[0][0][lane];   // +128 per layer, +32 per rot
    const float2*  ltab = &g_left[0][lane];     // +32 per layer

    double2 E[3][4], O[3][4];
    float2  LF[3];
    #define LDST(k, tt) {                                             \
        const double2* pE_ = tab + (tt) * 128;                        \
        E[k][0] = pE_[0];  E[k][1] = pE_[32];                         \
        E[k][2] = pE_[64]; E[k][3] = pE_[96];                         \
        const double2* pO_ = tab + ((tt) + 1) * 128;                  \
        O[k][0] = pO_[0];  O[k][1] = pO_[32];                         \
        O[k][2] = pO_[64]; O[k][3] = pO_[96];                         \
        LF[k] = ltab[((tt) + 1) * 32]; }

    LDST(0, 0) LDST(1, 2) LDST(2, 4)

    int t = 0;
    #pragma unroll 1
    for (int it = 0; it < 170; ++it) {       // 170 * 3 stages * 2 layers = 1020
        #pragma unroll
        for (int u = 0; u < 3; ++u) {
            // ---- even layer ----
            rotp(P[0], P[1], E[u][0]);
            rotp(P[2], P[3], E[u][1]);
            rotp(P[4], P[5], E[u][2]);
            rotp(P[6], P[7], E[u][3]);
            // ---- odd layer ----
            // parallel halo shuffles (post-even values, pre-odd updates)
            float v16  = __shfl_down_sync(0xffffffffu, lo_f(P[0]), 1); // right nbr v0
            float lv15 = __shfl_up_sync  (0xffffffffu, hi_f(P[7]), 1); // left  nbr v15
            rotp(P[1], P[2], O[u][0]);
            rotp(P[3], P[4], O[u][1]);
            rotp(P[5], P[6], O[u][2]);
            // boundary packed rot: (v7,v15) x (v8,v16)
            ull Q = pk(hi_f(P[0]), v16);
            rotp(P[7], Q, O[u][3]);
            // left gate updates v0 redundantly (nbr keeps its own half); lane0 identity
            float cl = LF[u].x, sl = LF[u].y;
            float nv0 = fmaf(cl, lo_f(P[0]), -(sl * lv15));
            P[0] = pk(nv0, lo_f(Q));         // (new v0, new v8); Q.hi discarded
            // prefetch 6 layers ahead
            LDST(u, t + 6 + 2 * u)
        }
        t += 6;
    }

    // epilogue: layer 1020 (even), ring slot 0
    rotp(P[0], P[1], E[0][0]);
    rotp(P[2], P[3], E[0][1]);
    rotp(P[4], P[5], E[0][2]);
    rotp(P[6], P[7], E[0][3]);

    // store + bias: wires 16L+k (lo halves), 16L+8+k (hi halves)
    {
        const float4* bb   = reinterpret_cast<const float4*>(bias) + lane * 4;
        float4*       outr = reinterpret_cast<float4*>(out + (size_t)row * N_WIRES) + lane * 4;
        float4 b0 = bb[0], b1 = bb[1], b2 = bb[2], b3 = bb[3];
        float4 o0, o1, o2, o3;
        o0.x = lo_f(P[0]) + b0.x; o0.y = lo_f(P[1]) + b0.y;
        o0.z = lo_f(P[2]) + b0.z; o0.w = lo_f(P[3]) + b0.w;
        o1.x = lo_f(P[4]) + b1.x; o1.y = lo_f(P[5]) + b1.y;
        o1.z = lo_f(P[6]) + b1.z; o1.w = lo_f(P[7]) + b1.w;
        o2.x = hi_f(P[0]) + b2.x; o2.y = hi_f(P[1]) + b2.y;
        o2.z = hi_f(P[2]) + b2.z; o2.w = hi_f(P[3]) + b2.w;
        o3.x = hi_f(P[4]) + b3.x; o3.y = hi_f(P[5]) + b3.y;
        o3.z = hi_f(P[6]) + b3.z; o3.w = hi_f(P[7]) + b3.w;
        outr[0] = o0; outr[1] = o1; outr[2] = o2; outr[3] = o3;
    }
    #undef LDST
}

extern "C" void kernel_launch(void* const* d_in, const int* in_sizes, int n_in,
                              void* d_out, int out_size) {
    const float* x      = (const float*)d_in[0];
    const float* thetas = (const float*)d_in[1];
    const float* bias   = (const float*)d_in[2];
    float* out = (float*)d_out;

    build_cs_kernel<<<T_PAD, 128>>>(thetas);

    int B = in_sizes[0] / N_WIRES;   // 256
    apply_kernel<<<B / 2, 64>>>(x, bias, out);
}

// round 3
// speedup vs baseline: 1.3664x; 1.3185x over previous
#include <cuda_runtime.h>

// Pyramid Givens circuit, n = m = 512, B = 256.
// Layer t in [0,1021): gates (i,i+1) for i ≡ t (mod 2), 0 <= i <= min(t, 1020-t).
// theta index: q=(t+i)/2, tidx = q(q+1)/2 + q - i.
// Gate: a' = c*a + s*b ; b' = c*b - s*a.

#define N_WIRES   512
#define CHUNK_L   6                    // layers per cp.async chunk (3 two-layer stages)
#define NCHUNK    172                  // 172 * 6 = 1032 layers (>= 1021; tail is identity)
#define T_PAD     (NCHUNK * CHUNK_L)   // 1032
#define LAYER_B   2304                 // 4*32*16 (rot double2) + 32*8 (left float2)
#define CHUNK_B   (CHUNK_L * LAYER_B)  // 13824
#define LEFT_OFF  2048

typedef unsigned long long ull;

// Per layer t (stride LAYER_B bytes):
//   [0,2048): rot cs, entry (r,lane) at r*512 + lane*16, as double2 {c2,s2} (f32x2 payloads)
//     even t, r=0..3: rot (P_2r,P_2r+1): lo gate wire 16L+2r, hi gate 16L+2r+8
//     odd t,  r=0..2: rot (P_2r+1,P_2r+2): lo gate 16L+2r+1, hi gate 16L+2r+9
//     odd t,  r=3:    boundary rot (P7,Q): lo gate 16L+7, hi gate 16L+15
//   [2048,2304): left-gate float2 (c,s) per lane: gate at wire 16L-1 (lane 0 -> identity)
// Inactive gates stored as identity (1,0).
__device__ __align__(16) char g_tab[T_PAD * LAYER_B];   // ~2.3 MB

__device__ __forceinline__ float2 cs_of(const float* __restrict__ th, int t, int i) {
    if (t <= 1020 && i >= 0 && i <= t && i <= 1020 - t && (((i ^ t) & 1) == 0)) {
        int q = (t + i) >> 1;
        int tidx = (q * (q + 1)) / 2 + q - i;
        float s, c;
        sincosf(th[tidx], &s, &c);
        return make_float2(c, s);
    }
    return make_float2(1.0f, 0.0f);
}

__global__ void build_cs_kernel(const float* __restrict__ thetas) {
    int t    = blockIdx.x;          // 0..T_PAD-1 (t > 1020 -> identity)
    int r    = threadIdx.x >> 5;    // 0..3
    int lane = threadIdx.x & 31;
    int base = 16 * lane;
    int ilo, ihi;
    if ((t & 1) == 0)      { ilo = base + 2 * r;     ihi = ilo + 8; }
    else if (r < 3)        { ilo = base + 2 * r + 1; ihi = ilo + 8; }
    else                   { ilo = base + 7;         ihi = base + 15; }
    float2 a = cs_of(thetas, t, ilo);
    float2 b = cs_of(thetas, t, ihi);
    float2* dst = reinterpret_cast<float2*>(g_tab + (size_t)t * LAYER_B + r * 512 + lane * 16);
    dst[0] = make_float2(a.x, b.x);   // c2 = (c_lo, c_hi)
    dst[1] = make_float2(a.y, b.y);   // s2 = (s_lo, s_hi)
    if (r == 3) {
        float2 lf = (lane == 0) ? make_float2(1.0f, 0.0f) : cs_of(thetas, t, base - 1);
        *reinterpret_cast<float2*>(g_tab + (size_t)t * LAYER_B + LEFT_OFF + lane * 8) = lf;
    }
}

// ---- f32x2 helpers ----
__device__ __forceinline__ ull mul2(ull a, ull b) {
    ull d; asm("mul.rn.f32x2 %0, %1, %2;" : "=l"(d) : "l"(a), "l"(b)); return d;
}
__device__ __forceinline__ ull fma2(ull a, ull b, ull c) {
    ull d; asm("fma.rn.f32x2 %0, %1, %2, %3;" : "=l"(d) : "l"(a), "l"(b), "l"(c)); return d;
}
__device__ __forceinline__ float lo_f(ull p) {
    float lo, hi; asm("mov.b64 {%0, %1}, %2;" : "=f"(lo), "=f"(hi) : "l"(p)); return lo;
}
__device__ __forceinline__ float hi_f(ull p) {
    float lo, hi; asm("mov.b64 {%0, %1}, %2;" : "=f"(lo), "=f"(hi) : "l"(p)); return hi;
}
__device__ __forceinline__ ull pk(float lo, float hi) {
    ull d; asm("mov.b64 %0, {%1, %2};" : "=l"(d) : "f"(lo), "f"(hi)); return d;
}

#define SGNMASK 0x8000000080000000ULL

// Packed Givens: a' = c*a + s*b ; b' = c*b - s*a
__device__ __forceinline__ void rotp(ull& a, ull& b, double2 cs) {
    ull c2 = __double_as_longlong(cs.x);
    ull s2 = __double_as_longlong(cs.y);
    ull t1 = mul2(s2, b);
    ull na = fma2(c2, a, t1);
    ull t2 = mul2(s2, a) ^ SGNMASK;      // -s*a
    b = fma2(c2, b, t2);
    a = na;
}

__device__ __forceinline__ void cp16(char* dst_smem, const char* src) {
    unsigned d = (unsigned)__cvta_generic_to_shared(dst_smem);
    asm volatile("cp.async.cg.shared.global [%0], [%1], 16;" :: "r"(d), "l"(src));
}
__device__ __forceinline__ void cp_commit() { asm volatile("cp.async.commit_group;"); }
__device__ __forceinline__ void cp_wait1()  { asm volatile("cp.async.wait_group 1;" ::: "memory"); }

// One warp per batch row, 2 warps per CTA. cs table staged global->smem via
// a 3-buffer cp.async pipeline (2 chunks in flight), consumed via LDS.128.
__global__ void __launch_bounds__(64, 1) apply_kernel(
    const float* __restrict__ x,
    const float* __restrict__ bias,
    float* __restrict__ out)
{
    __shared__ __align__(16) char sbuf[3][CHUNK_B];   // 41472 B

    const int tid  = threadIdx.x;
    const int lane = tid & 31;
    const int row  = blockIdx.x * 2 + (tid >> 5);

    // Load row, pack P[k] = (v_k, v_{k+8}); lane owns wires [16L, 16L+15]
    ull P[8];
    {
        float v[16];
        const float4* xr = reinterpret_cast<const float4*>(x + (size_t)row * N_WIRES) + lane * 4;
        #pragma unroll
        for (int j = 0; j < 4; ++j) {
            float4 f = xr[j];
            v[4*j+0] = f.x; v[4*j+1] = f.y; v[4*j+2] = f.z; v[4*j+3] = f.w;
        }
        #pragma unroll
        for (int k = 0; k < 8; ++k) P[k] = pk(v[k], v[k + 8]);
    }

    // prologue: chunks 0,1 -> buffers 0,1
    #pragma unroll 1
    for (int pc = 0; pc < 2; ++pc) {
        const char* src = g_tab + (size_t)pc * CHUNK_B;
        for (int off = tid * 16; off < CHUNK_B; off += 64 * 16)
            cp16(&sbuf[pc][off], src + off);
        cp_commit();
    }

    int rb = 0;   // buffer holding chunk c
    int ib = 2;   // buffer to fill with chunk c+2
    #pragma unroll 1
    for (int c = 0; c < NCHUNK; ++c) {
        cp_wait1();
        __syncthreads();

        // issue chunk c+2 into ib (holds chunk c-1, finished last iteration)
        if (c + 2 < NCHUNK) {
            const char* src = g_tab + (size_t)(c + 2) * CHUNK_B;
            for (int off = tid * 16; off < CHUNK_B; off += 64 * 16)
                cp16(&sbuf[ib][off], src + off);
        }
        cp_commit();   // always commit (possibly empty group) to keep wait_group counting

        const char* cb = sbuf[rb];
        #pragma unroll
        for (int s = 0; s < CHUNK_L / 2; ++s) {
            const char* le = cb + (2 * s) * LAYER_B;
            const char* lo = le + LAYER_B;
            double2 E0 = *reinterpret_cast<const double2*>(le +   0 + lane * 16);
            double2 E1 = *reinterpret_cast<const double2*>(le + 512 + lane * 16);
            double2 E2 = *reinterpret_cast<const double2*>(le + 1024 + lane * 16);
            double2 E3 = *reinterpret_cast<const double2*>(le + 1536 + lane * 16);
            double2 O0 = *reinterpret_cast<const double2*>(lo +   0 + lane * 16);
            double2 O1 = *reinterpret_cast<const double2*>(lo + 512 + lane * 16);
            double2 O2 = *reinterpret_cast<const double2*>(lo + 1024 + lane * 16);
            double2 O3 = *reinterpret_cast<const double2*>(lo + 1536 + lane * 16);
            float2  LF = *reinterpret_cast<const float2*>(lo + LEFT_OFF + lane * 8);

            // ---- even layer ----
            rotp(P[0], P[1], E0);
            rotp(P[2], P[3], E1);
            rotp(P[4], P[5], E2);
            rotp(P[6], P[7], E3);
            // ---- odd layer ----
            float v16  = __shfl_down_sync(0xffffffffu, lo_f(P[0]), 1); // right nbr v0
            float lv15 = __shfl_up_sync  (0xffffffffu, hi_f(P[7]), 1); // left  nbr v15
            rotp(P[1], P[2], O0);
            rotp(P[3], P[4], O1);
            rotp(P[5], P[6], O2);
            ull Q = pk(hi_f(P[0]), v16);          // (v8, v16)
            rotp(P[7], Q, O3);                    // boundary: (v7,v15) x (v8,v16)
            // left gate updates v0 redundantly; lane 0 identity
            float nv0 = fmaf(LF.x, lo_f(P[0]), -(LF.y * lv15));
            P[0] = pk(nv0, lo_f(Q));              // (new v0, new v8)
        }

        rb = (rb == 2) ? 0 : rb + 1;
        ib = (ib == 2) ? 0 : ib + 1;
    }

    // store + bias: wires 16L+k (lo halves), 16L+8+k (hi halves)
    {
        const float4* bb   = reinterpret_cast<const float4*>(bias) + lane * 4;
        float4*       outr = reinterpret_cast<float4*>(out + (size_t)row * N_WIRES) + lane * 4;
        float4 b0 = bb[0], b1 = bb[1], b2 = bb[2], b3 = bb[3];
        float4 o0, o1, o2, o3;
        o0.x = lo_f(P[0]) + b0.x; o0.y = lo_f(P[1]) + b0.y;
        o0.z = lo_f(P[2]) + b0.z; o0.w = lo_f(P[3]) + b0.w;
        o1.x = lo_f(P[4]) + b1.x; o1.y = lo_f(P[5]) + b1.y;
        o1.z = lo_f(P[6]) + b1.z; o1.w = lo_f(P[7]) + b1.w;
        o2.x = hi_f(P[0]) + b2.x; o2.y = hi_f(P[1]) + b2.y;
        o2.z = hi_f(P[2]) + b2.z; o2.w = hi_f(P[3]) + b2.w;
        o3.x = hi_f(P[4]) + b3.x; o3.y = hi_f(P[5]) + b3.y;
        o3.z = hi_f(P[6]) + b3.z; o3.w = hi_f(P[7]) + b3.w;
        outr[0] = o0; outr[1] = o1; outr[2] = o2; outr[3] = o3;
    }
}

extern "C" void kernel_launch(void* const* d_in, const int* in_sizes, int n_in,
                              void* d_out, int out_size) {
    const float* x      = (const float*)d_in[0];
    const float* thetas = (const float*)d_in[1];
    const float* bias   = (const float*)d_in[2];
    float* out = (float*)d_out;

    build_cs_kernel<<<T_PAD, 128>>>(thetas);

    int B = in_sizes[0] / N_WIRES;   // 256
    apply_kernel<<<B / 2, 64>>>(x, bias, out);
}